// round 1
// baseline (speedup 1.0000x reference)
#include <cuda_runtime.h>
#include <cuda_bf16.h>
#include <math.h>

// Problem constants
#define S_ 2048
#define D_ 1280
#define H_ 16
#define HD_ 80
#define I_ 5120
#define NQKV_ 3840
#define EPS_ 1e-6f
#define SCALE_ 0.11180339887498949f  // 80^-0.5

// ---------------- device scratch (no allocation allowed) ----------------
__device__ float g_h[S_ * D_];                       // LN output          10.5 MB
__device__ float g_qkv[S_ * NQKV_];                  // qkv proj           31.5 MB
__device__ float g_q[H_ * S_ * HD_];                 // per-head Q (roped) 10.5 MB
__device__ float g_k[H_ * S_ * HD_];                 // per-head K (roped) 10.5 MB
__device__ float g_v[H_ * S_ * HD_];                 // per-head V         10.5 MB
__device__ float g_scores[(size_t)H_ * S_ * S_];     // attn scores        268 MB
__device__ float g_attn[S_ * D_];                    // attn out [S,D]     10.5 MB
__device__ float g_mlp[S_ * I_];                     // fc1 out            42 MB

// ---------------- LayerNorm: one block per row ----------------
__global__ void layernorm_kernel(const float* __restrict__ x,
                                 const float* __restrict__ g,
                                 const float* __restrict__ b,
                                 float* __restrict__ out) {
    const int row = blockIdx.x;
    const int t = threadIdx.x;
    __shared__ float srow[D_];
    __shared__ float red[256];

    float local = 0.f;
    for (int i = t; i < D_; i += 256) {
        float v = x[(size_t)row * D_ + i];
        srow[i] = v;
        local += v;
    }
    red[t] = local;
    __syncthreads();
    for (int s = 128; s > 0; s >>= 1) {
        if (t < s) red[t] += red[t + s];
        __syncthreads();
    }
    const float mean = red[0] * (1.0f / D_);
    __syncthreads();

    local = 0.f;
    for (int i = t; i < D_; i += 256) {
        float dv = srow[i] - mean;
        local += dv * dv;
    }
    red[t] = local;
    __syncthreads();
    for (int s = 128; s > 0; s >>= 1) {
        if (t < s) red[t] += red[t + s];
        __syncthreads();
    }
    const float inv = rsqrtf(red[0] * (1.0f / D_) + EPS_);

    for (int i = t; i < D_; i += 256) {
        out[(size_t)row * D_ + i] = (srow[i] - mean) * inv * g[i] + b[i];
    }
}

// ---------------- RoPE + head split ----------------
// qkv layout per row s: [3][H][HD] in the 3840 dim.
__global__ void rope_split_kernel(const float* __restrict__ qkv,
                                  const float* __restrict__ cosp,
                                  const float* __restrict__ sinp,
                                  float* __restrict__ Q,
                                  float* __restrict__ K,
                                  float* __restrict__ V) {
    int i = blockIdx.x * blockDim.x + threadIdx.x;
    if (i >= S_ * D_) return;
    const int s = i / D_;
    const int r = i % D_;
    const int h = r / HD_;
    const int d = r % HD_;

    const float c = cosp[s * HD_ + d];
    const float sn = sinp[s * HD_ + d];
    const size_t base = (size_t)s * NQKV_;

    const int d2 = (d < HD_ / 2) ? d + HD_ / 2 : d - HD_ / 2;
    const float sign = (d < HD_ / 2) ? -1.f : 1.f;

    const float q = qkv[base + r];
    const float qp = qkv[base + h * HD_ + d2];
    const float k = qkv[base + D_ + r];
    const float kp = qkv[base + D_ + h * HD_ + d2];

    const size_t o = (size_t)h * S_ * HD_ + (size_t)s * HD_ + d;
    Q[o] = q * c + sign * qp * sn;
    K[o] = k * c + sign * kp * sn;
    V[o] = qkv[base + 2 * D_ + r];
}

// ---------------- row softmax (row length S_=2048, 256 threads, 8/thread) ----------------
__global__ void softmax_kernel(float* __restrict__ Sc) {
    const size_t row = blockIdx.x;
    float* p = Sc + row * S_;
    const int t = threadIdx.x;
    __shared__ float red[256];

    float v[8];
    float m = -1e30f;
#pragma unroll
    for (int i = 0; i < 8; i++) {
        v[i] = p[t + i * 256];
        m = fmaxf(m, v[i]);
    }
    red[t] = m;
    __syncthreads();
    for (int s = 128; s > 0; s >>= 1) {
        if (t < s) red[t] = fmaxf(red[t], red[t + s]);
        __syncthreads();
    }
    m = red[0];
    __syncthreads();

    float sum = 0.f;
#pragma unroll
    for (int i = 0; i < 8; i++) {
        v[i] = expf(v[i] - m);
        sum += v[i];
    }
    red[t] = sum;
    __syncthreads();
    for (int s = 128; s > 0; s >>= 1) {
        if (t < s) red[t] += red[t + s];
        __syncthreads();
    }
    const float inv = 1.0f / red[0];
#pragma unroll
    for (int i = 0; i < 8; i++) {
        p[t + i * 256] = v[i] * inv;
    }
}

// ---------------- generic tiled SGEMM ----------------
// C[M,N] = alpha * A[M,K] x B  (B is [K,N] if !TB, else B is [N,K] and we use B^T)
// EPI: 0 = store   1 = +bias   2 = C += acc+bias (residual)   3 = gelu(acc+bias)
template <int BM, int BN, int BK, int TM, int TN, bool TB, int EPI>
__global__ void __launch_bounds__((BM / TM) * (BN / TN))
gemm_kernel(const float* __restrict__ A, const float* __restrict__ B,
            const float* __restrict__ bias, float* __restrict__ C,
            int M, int N, int K, int lda, int ldb, int ldc,
            long long sA, long long sB, long long sC, float alpha) {
    constexpr int NT = (BM / TM) * (BN / TN);
    constexpr int NX = BN / TN;

    __shared__ float As[BK][BM];
    __shared__ float Bs[BK][BN];

    const int t = threadIdx.x;
    const int bz = blockIdx.z;
    A += (size_t)bz * sA;
    B += (size_t)bz * sB;
    C += (size_t)bz * sC;

    const int row0 = blockIdx.y * BM;
    const int col0 = blockIdx.x * BN;
    const int tx = t % NX;
    const int ty = t / NX;

    float acc[TM][TN];
#pragma unroll
    for (int i = 0; i < TM; i++)
#pragma unroll
        for (int j = 0; j < TN; j++) acc[i][j] = 0.f;

    for (int k0 = 0; k0 < K; k0 += BK) {
        // A tile: As[kk][m]  (consecutive threads read consecutive K -> coalesced)
#pragma unroll
        for (int e = t; e < BM * BK; e += NT) {
            int m = e / BK, kk = e % BK;
            int gr = row0 + m, gk = k0 + kk;
            As[kk][m] = (gr < M && gk < K) ? A[(size_t)gr * lda + gk] : 0.f;
        }
        if (!TB) {
            // B[K,N]: consecutive threads read consecutive N -> coalesced
#pragma unroll
            for (int e = t; e < BK * BN; e += NT) {
                int kk = e / BN, n = e % BN;
                int gk = k0 + kk, gc = col0 + n;
                Bs[kk][n] = (gk < K && gc < N) ? B[(size_t)gk * ldb + gc] : 0.f;
            }
        } else {
            // B[N,K] (use B^T): consecutive threads read consecutive K -> coalesced
#pragma unroll
            for (int e = t; e < BK * BN; e += NT) {
                int n = e / BK, kk = e % BK;
                int gc = col0 + n, gk = k0 + kk;
                Bs[kk][n] = (gc < N && gk < K) ? B[(size_t)gc * ldb + gk] : 0.f;
            }
        }
        __syncthreads();

#pragma unroll
        for (int kk = 0; kk < BK; kk++) {
            float a[TM], bv[TN];
#pragma unroll
            for (int i = 0; i < TM; i++) a[i] = As[kk][ty * TM + i];
#pragma unroll
            for (int j = 0; j < TN; j++) bv[j] = Bs[kk][tx * TN + j];
#pragma unroll
            for (int i = 0; i < TM; i++)
#pragma unroll
                for (int j = 0; j < TN; j++) acc[i][j] += a[i] * bv[j];
        }
        __syncthreads();
    }

#pragma unroll
    for (int i = 0; i < TM; i++) {
        int r = row0 + ty * TM + i;
        if (r >= M) continue;
#pragma unroll
        for (int j = 0; j < TN; j++) {
            int c = col0 + tx * TN + j;
            if (c >= N) continue;
            float v = alpha * acc[i][j];
            size_t idx = (size_t)r * ldc + c;
            if (EPI == 0) {
                C[idx] = v;
            } else if (EPI == 1) {
                C[idx] = v + bias[c];
            } else if (EPI == 2) {
                C[idx] = C[idx] + v + bias[c];
            } else {
                float gv = v + bias[c];
                C[idx] = 0.5f * gv * (1.0f + erff(gv * 0.70710678118654752f));
            }
        }
    }
}

// ---------------- host-side launch ----------------
extern "C" void kernel_launch(void* const* d_in, const int* in_sizes, int n_in,
                              void* d_out, int out_size) {
    const float* hidden = (const float*)d_in[0];
    const float* cosp   = (const float*)d_in[1];
    const float* sinp   = (const float*)d_in[2];
    const float* qkv_w  = (const float*)d_in[3];
    const float* qkv_b  = (const float*)d_in[4];
    const float* proj_w = (const float*)d_in[5];
    const float* proj_b = (const float*)d_in[6];
    const float* ln1_g  = (const float*)d_in[7];
    const float* ln1_b  = (const float*)d_in[8];
    const float* ln2_g  = (const float*)d_in[9];
    const float* ln2_b  = (const float*)d_in[10];
    const float* fc1_w  = (const float*)d_in[11];
    const float* fc1_b  = (const float*)d_in[12];
    const float* fc2_w  = (const float*)d_in[13];
    const float* fc2_b  = (const float*)d_in[14];

    float* x = (float*)d_out;

    float *p_h, *p_qkv, *p_q, *p_k, *p_v, *p_sc, *p_at, *p_mlp;
    cudaGetSymbolAddress((void**)&p_h, g_h);
    cudaGetSymbolAddress((void**)&p_qkv, g_qkv);
    cudaGetSymbolAddress((void**)&p_q, g_q);
    cudaGetSymbolAddress((void**)&p_k, g_k);
    cudaGetSymbolAddress((void**)&p_v, g_v);
    cudaGetSymbolAddress((void**)&p_sc, g_scores);
    cudaGetSymbolAddress((void**)&p_at, g_attn);
    cudaGetSymbolAddress((void**)&p_mlp, g_mlp);

    // x = hidden_states
    cudaMemcpyAsync(x, hidden, (size_t)S_ * D_ * sizeof(float),
                    cudaMemcpyDeviceToDevice);

    for (int l = 0; l < 2; l++) {
        const float* qw = qkv_w + (size_t)l * D_ * NQKV_;
        const float* qb = qkv_b + (size_t)l * NQKV_;
        const float* pw = proj_w + (size_t)l * D_ * D_;
        const float* pb = proj_b + (size_t)l * D_;
        const float* g1 = ln1_g + (size_t)l * D_;
        const float* b1 = ln1_b + (size_t)l * D_;
        const float* g2 = ln2_g + (size_t)l * D_;
        const float* b2 = ln2_b + (size_t)l * D_;
        const float* f1w = fc1_w + (size_t)l * D_ * I_;
        const float* f1b = fc1_b + (size_t)l * I_;
        const float* f2w = fc2_w + (size_t)l * I_ * D_;
        const float* f2b = fc2_b + (size_t)l * D_;

        // LN1
        layernorm_kernel<<<S_, 256>>>(x, g1, b1, p_h);

        // qkv = h @ qkv_w + b   [2048,3840]
        gemm_kernel<128, 128, 16, 8, 8, false, 1>
            <<<dim3(NQKV_ / 128, S_ / 128, 1), 256>>>(
                p_h, qw, qb, p_qkv, S_, NQKV_, D_, D_, NQKV_, NQKV_, 0, 0, 0, 1.f);

        // RoPE + head split
        rope_split_kernel<<<(S_ * D_ + 255) / 256, 256>>>(p_qkv, cosp, sinp,
                                                          p_q, p_k, p_v);

        // scores = Q @ K^T * SCALE, batched over heads
        gemm_kernel<128, 128, 16, 8, 8, true, 0>
            <<<dim3(S_ / 128, S_ / 128, H_), 256>>>(
                p_q, p_k, nullptr, p_sc, S_, S_, HD_, HD_, HD_, S_,
                (long long)S_ * HD_, (long long)S_ * HD_, (long long)S_ * S_,
                SCALE_);

        // softmax over rows
        softmax_kernel<<<H_ * S_, 256>>>(p_sc);

        // O = P @ V  -> write into [S, D] layout via ldc=D_, per-head col offset
        gemm_kernel<64, 80, 16, 4, 5, false, 0>
            <<<dim3(1, S_ / 64, H_), 256>>>(
                p_sc, p_v, nullptr, p_at, S_, HD_, S_, S_, HD_, D_,
                (long long)S_ * S_, (long long)S_ * HD_, (long long)HD_, 1.f);

        // x += O @ proj_w + b
        gemm_kernel<128, 128, 16, 8, 8, false, 2>
            <<<dim3(D_ / 128, S_ / 128, 1), 256>>>(
                p_at, pw, pb, x, S_, D_, D_, D_, D_, D_, 0, 0, 0, 1.f);

        // LN2
        layernorm_kernel<<<S_, 256>>>(x, g2, b2, p_h);

        // mlp = gelu(h @ fc1_w + b)
        gemm_kernel<128, 128, 16, 8, 8, false, 3>
            <<<dim3(I_ / 128, S_ / 128, 1), 256>>>(
                p_h, f1w, f1b, p_mlp, S_, I_, D_, D_, I_, I_, 0, 0, 0, 1.f);

        // x += mlp @ fc2_w + b
        gemm_kernel<128, 128, 16, 8, 8, false, 2>
            <<<dim3(D_ / 128, S_ / 128, 1), 256>>>(
                p_mlp, f2w, f2b, x, S_, D_, I_, I_, D_, D_, 0, 0, 0, 1.f);
    }
}

// round 4
// speedup vs baseline: 3.1278x; 3.1278x over previous
#include <cuda_runtime.h>
#include <cuda_bf16.h>
#include <math.h>
#include <stdint.h>

// Problem constants
#define S_ 2048
#define D_ 1280
#define H_ 16
#define HD_ 80
#define HDP_ 128          // padded head dim for score-MMA K
#define I_ 5120
#define NQKV_ 3840
#define EPS_ 1e-6f
#define SCALE_ 0.11180339887498949f  // 80^-0.5

typedef __nv_bfloat16 bf16;

// ===================== device scratch (no allocation allowed) =====================
__device__ float g_qkv[S_ * NQKV_];                  // qkv proj fp32
__device__ bf16  g_hh[S_ * D_],  g_hl[S_ * D_];      // LN out split
__device__ bf16  g_qh[H_ * S_ * HDP_], g_ql[H_ * S_ * HDP_];
__device__ bf16  g_kh[H_ * S_ * HDP_], g_kl[H_ * S_ * HDP_];
__device__ bf16  g_vth[H_ * HD_ * S_], g_vtl[H_ * HD_ * S_];   // V^T per head
__device__ float g_scores[(size_t)H_ * S_ * S_];     // 268 MB
__device__ bf16  g_ph[(size_t)H_ * S_ * S_], g_pl[(size_t)H_ * S_ * S_];
__device__ bf16  g_ah[S_ * D_],  g_al[S_ * D_];      // attn out split
__device__ bf16  g_mh[S_ * I_],  g_ml[S_ * I_];      // mlp hidden split
__device__ bf16  g_wqh[NQKV_ * D_], g_wql[NQKV_ * D_];
__device__ bf16  g_wph[D_ * D_],    g_wpl[D_ * D_];
__device__ bf16  g_w1h[I_ * D_],    g_w1l[I_ * D_];
__device__ bf16  g_w2h[D_ * I_],    g_w2l[D_ * I_];

__device__ __forceinline__ void bsplit(float v, bf16& h, bf16& l) {
    h = __float2bfloat16(v);
    l = __float2bfloat16(v - __bfloat162float(h));
}

__device__ __forceinline__ uint32_t smem_to_u32(const void* smem_ptr) {
    uint32_t addr;
    asm("{ .reg .u64 tmp; cvta.to.shared.u64 tmp, %1; cvt.u32.u64 %0, tmp; }"
        : "=r"(addr) : "l"(smem_ptr));
    return addr;
}

__device__ __forceinline__ void ldsm4(uint32_t (&r)[4], uint32_t addr) {
    asm volatile("ldmatrix.sync.aligned.m8n8.x4.shared.b16 {%0,%1,%2,%3}, [%4];"
                 : "=r"(r[0]), "=r"(r[1]), "=r"(r[2]), "=r"(r[3]) : "r"(addr));
}

__device__ __forceinline__ void mma16816(float (&d)[4], const uint32_t (&a)[4],
                                         const uint32_t* b) {
    asm volatile(
        "mma.sync.aligned.m16n8k16.row.col.f32.bf16.bf16.f32 "
        "{%0,%1,%2,%3}, {%4,%5,%6,%7}, {%8,%9}, {%0,%1,%2,%3};"
        : "+f"(d[0]), "+f"(d[1]), "+f"(d[2]), "+f"(d[3])
        : "r"(a[0]), "r"(a[1]), "r"(a[2]), "r"(a[3]), "r"(b[0]), "r"(b[1]));
}

// ===================== LayerNorm -> bf16 split =====================
__global__ void ln_split_kernel(const float* __restrict__ x,
                                const float* __restrict__ g,
                                const float* __restrict__ b,
                                bf16* __restrict__ oh, bf16* __restrict__ ol) {
    const int row = blockIdx.x;
    const int t = threadIdx.x;
    __shared__ float srow[D_];
    __shared__ float red[256];

    float local = 0.f;
    for (int i = t; i < D_; i += 256) {
        float v = x[(size_t)row * D_ + i];
        srow[i] = v;
        local += v;
    }
    red[t] = local;
    __syncthreads();
    for (int s = 128; s > 0; s >>= 1) { if (t < s) red[t] += red[t + s]; __syncthreads(); }
    const float mean = red[0] * (1.0f / D_);
    __syncthreads();

    local = 0.f;
    for (int i = t; i < D_; i += 256) { float dv = srow[i] - mean; local += dv * dv; }
    red[t] = local;
    __syncthreads();
    for (int s = 128; s > 0; s >>= 1) { if (t < s) red[t] += red[t + s]; __syncthreads(); }
    const float inv = rsqrtf(red[0] * (1.0f / D_) + EPS_);

    for (int i = t; i < D_; i += 256) {
        float v = (srow[i] - mean) * inv * g[i] + b[i];
        bf16 h, l; bsplit(v, h, l);
        oh[(size_t)row * D_ + i] = h;
        ol[(size_t)row * D_ + i] = l;
    }
}

// ===================== weight transpose + split: w[K][N] -> Wt[N][K] =====================
__global__ void wsplit_T_kernel(const float* __restrict__ w,
                                bf16* __restrict__ oh, bf16* __restrict__ ol,
                                int K, int N) {
    __shared__ float tile[32][33];
    int k0 = blockIdx.y * 32, n0 = blockIdx.x * 32;
    int tx = threadIdx.x, ty = threadIdx.y;
#pragma unroll
    for (int j = 0; j < 4; j++)
        tile[ty + j * 8][tx] = w[(size_t)(k0 + ty + j * 8) * N + n0 + tx];
    __syncthreads();
#pragma unroll
    for (int j = 0; j < 4; j++) {
        int n = ty + j * 8;
        float v = tile[tx][n];
        bf16 h, l; bsplit(v, h, l);
        size_t o = (size_t)(n0 + n) * K + k0 + tx;
        oh[o] = h; ol[o] = l;
    }
}

// ===================== RoPE + head split + V transpose =====================
__global__ void rope_split_kernel(const float* __restrict__ qkv,
                                  const float* __restrict__ cosp,
                                  const float* __restrict__ sinp,
                                  bf16* __restrict__ Qh, bf16* __restrict__ Ql,
                                  bf16* __restrict__ Kh, bf16* __restrict__ Kl,
                                  bf16* __restrict__ Vth, bf16* __restrict__ Vtl) {
    int i = blockIdx.x * blockDim.x + threadIdx.x;
    if (i >= S_ * D_) return;
    const int s = i / D_;
    const int r = i % D_;
    const int h = r / HD_;
    const int d = r % HD_;

    const float c = cosp[s * HD_ + d];
    const float sn = sinp[s * HD_ + d];
    const size_t base = (size_t)s * NQKV_;

    const int d2 = (d < HD_ / 2) ? d + HD_ / 2 : d - HD_ / 2;
    const float sign = (d < HD_ / 2) ? -1.f : 1.f;

    const float q  = qkv[base + r];
    const float qp = qkv[base + h * HD_ + d2];
    const float k  = qkv[base + D_ + r];
    const float kp = qkv[base + D_ + h * HD_ + d2];
    const float v  = qkv[base + 2 * D_ + r];

    const float rq = q * c + sign * qp * sn;
    const float rk = k * c + sign * kp * sn;

    const size_t oq = ((size_t)h * S_ + s) * HDP_ + d;   // padded cols [80,128) stay 0
    bf16 hh, ll;
    bsplit(rq, hh, ll); Qh[oq] = hh; Ql[oq] = ll;
    bsplit(rk, hh, ll); Kh[oq] = hh; Kl[oq] = ll;
    const size_t ov = ((size_t)h * HD_ + d) * S_ + s;
    bsplit(v, hh, ll);  Vth[ov] = hh; Vtl[ov] = ll;
}

// zero-fill the padded Q/K columns once (rope only writes d<80)
__global__ void zero_pad_qk(bf16* __restrict__ Qh, bf16* __restrict__ Ql,
                            bf16* __restrict__ Kh, bf16* __restrict__ Kl) {
    int i = blockIdx.x * blockDim.x + threadIdx.x;
    int n = H_ * S_ * (HDP_ - HD_);
    if (i >= n) return;
    int row = i / (HDP_ - HD_);
    int d = HD_ + i % (HDP_ - HD_);
    size_t o = (size_t)row * HDP_ + d;
    Qh[o] = __float2bfloat16(0.f); Ql[o] = __float2bfloat16(0.f);
    Kh[o] = __float2bfloat16(0.f); Kl[o] = __float2bfloat16(0.f);
}

// ===================== row softmax -> bf16 split probs =====================
__global__ void softmax_kernel(const float* __restrict__ Sc,
                               bf16* __restrict__ Ph, bf16* __restrict__ Pl) {
    const size_t row = blockIdx.x;
    const float* p = Sc + row * S_;
    const int t = threadIdx.x;
    __shared__ float red[256];

    float v[8];
    float m = -1e30f;
#pragma unroll
    for (int i = 0; i < 8; i++) { v[i] = p[t + i * 256]; m = fmaxf(m, v[i]); }
    red[t] = m;
    __syncthreads();
    for (int s = 128; s > 0; s >>= 1) { if (t < s) red[t] = fmaxf(red[t], red[t + s]); __syncthreads(); }
    m = red[0];
    __syncthreads();

    float sum = 0.f;
#pragma unroll
    for (int i = 0; i < 8; i++) { v[i] = expf(v[i] - m); sum += v[i]; }
    red[t] = sum;
    __syncthreads();
    for (int s = 128; s > 0; s >>= 1) { if (t < s) red[t] += red[t + s]; __syncthreads(); }
    const float inv = 1.0f / red[0];
#pragma unroll
    for (int i = 0; i < 8; i++) {
        float pv = v[i] * inv;
        bf16 h, l; bsplit(pv, h, l);
        size_t o = row * S_ + t + i * 256;
        Ph[o] = h; Pl[o] = l;
    }
}

// ===================== mma.sync bf16x3 GEMM =====================
// C[M, N] = alpha * A[M,K] @ B[N,K]^T   (A,B K-major bf16 hi/lo pairs)
// CTA tile 128x128, BK=32, 8 warps each 32x64. cp.async double-buffered.
// EPI: 0 = C=v+bias  1 = C=v  2 = C+=v+bias  3 = split-store  4 = gelu(v+bias) split-store
#define TILE_B 10240          // 128 rows * 80B pitch
#define BUF_B (4 * TILE_B)    // Ah, Al, Bh, Bl
#define GEMM_SMEM (2 * BUF_B) // 81920

template <int EPI>
__global__ void __launch_bounds__(256, 1)
gemm_mma(const bf16* __restrict__ Agh, const bf16* __restrict__ Agl,
         const bf16* __restrict__ Bgh, const bf16* __restrict__ Bgl,
         const float* __restrict__ bias,
         float* __restrict__ C, bf16* __restrict__ Ch, bf16* __restrict__ Cl,
         int Ntot, int K, int lda, int ldb, int ldc,
         long long sA, long long sB, long long sC, float alpha) {
    extern __shared__ __align__(16) char smem[];
    const uint32_t sbase = smem_to_u32(smem);
    const int tid = threadIdx.x;
    const int wid = tid >> 5;
    const int lane = tid & 31;
    const int warp_m = wid & 3;   // 4 x 32 rows
    const int warp_n = wid >> 2;  // 2 x 64 cols
    const int bz = blockIdx.z;

    Agh += (size_t)bz * sA; Agl += (size_t)bz * sA;
    Bgh += (size_t)bz * sB; Bgl += (size_t)bz * sB;
    const size_t coff = (size_t)bz * sC;
    const int row0 = blockIdx.y * 128;
    const int col0 = blockIdx.x * 128;

    // ldmatrix lane offsets (bytes) within a tile
    const uint32_t a_off = (uint32_t)(((lane & 15) * 40 + (lane >> 4) * 8) * 2);
    const uint32_t b_off = (uint32_t)(((((lane & 7) | ((lane >> 4) << 3)) * 40) +
                                      (((lane >> 3) & 1) * 8)) * 2);

    auto load_chunk = [&](int kc, int buf) {
        const int k0 = kc << 5;
        const uint32_t dbase = sbase + (uint32_t)buf * BUF_B;
#pragma unroll
        for (int it = 0; it < 8; it++) {
            int e = it * 256 + tid;
            int t = e >> 9;
            int idx = e & 511;
            int row = idx >> 2;
            int c8 = idx & 3;
            const bf16* src;
            int sz = 16;
            if (t == 0)      src = Agh + (size_t)(row0 + row) * lda + k0 + c8 * 8;
            else if (t == 1) src = Agl + (size_t)(row0 + row) * lda + k0 + c8 * 8;
            else {
                int br = col0 + row;
                if (br >= Ntot) { br = col0; sz = 0; }
                src = (t == 2 ? Bgh : Bgl) + (size_t)br * ldb + k0 + c8 * 8;
            }
            uint32_t dst = dbase + (uint32_t)t * TILE_B + (uint32_t)(row * 80 + c8 * 16);
            asm volatile("cp.async.cg.shared.global [%0], [%1], 16, %2;"
                         :: "r"(dst), "l"(src), "r"(sz));
        }
    };

    float acc[2][8][4];
#pragma unroll
    for (int mi = 0; mi < 2; mi++)
#pragma unroll
        for (int nj = 0; nj < 8; nj++)
#pragma unroll
            for (int c = 0; c < 4; c++) acc[mi][nj][c] = 0.f;

    const int NC = K >> 5;
    load_chunk(0, 0);
    asm volatile("cp.async.commit_group;" ::: "memory");

    for (int kc = 0; kc < NC; kc++) {
        const int buf = kc & 1;
        if (kc + 1 < NC) {
            load_chunk(kc + 1, buf ^ 1);
            asm volatile("cp.async.commit_group;" ::: "memory");
            asm volatile("cp.async.wait_group 1;" ::: "memory");
        } else {
            asm volatile("cp.async.wait_group 0;" ::: "memory");
        }
        __syncthreads();

        const uint32_t bofs = sbase + (uint32_t)buf * BUF_B;
#pragma unroll
        for (int ks = 0; ks < 2; ks++) {
            uint32_t ah[2][4], al[2][4], bh[4][4], bl[4][4];
#pragma unroll
            for (int mi = 0; mi < 2; mi++) {
                uint32_t ad = bofs + (uint32_t)((warp_m * 32 + mi * 16) * 80 + ks * 32) + a_off;
                ldsm4(ah[mi], ad);
                ldsm4(al[mi], ad + TILE_B);
            }
#pragma unroll
            for (int ni = 0; ni < 4; ni++) {
                uint32_t bd = bofs + 2 * TILE_B +
                              (uint32_t)((warp_n * 64 + ni * 16) * 80 + ks * 32) + b_off;
                ldsm4(bh[ni], bd);
                ldsm4(bl[ni], bd + TILE_B);
            }
#pragma unroll
            for (int mi = 0; mi < 2; mi++)
#pragma unroll
                for (int nj = 0; nj < 8; nj++) {
                    const uint32_t* bhp = &bh[nj >> 1][(nj & 1) * 2];
                    const uint32_t* blp = &bl[nj >> 1][(nj & 1) * 2];
                    mma16816(acc[mi][nj], ah[mi], bhp);
                    mma16816(acc[mi][nj], ah[mi], blp);
                    mma16816(acc[mi][nj], al[mi], bhp);
                }
        }
        __syncthreads();
    }

    // ---- epilogue ----
    const int gid = lane >> 2, tig = lane & 3;
#pragma unroll
    for (int mi = 0; mi < 2; mi++) {
#pragma unroll
        for (int hh = 0; hh < 2; hh++) {
            const int r = row0 + warp_m * 32 + mi * 16 + gid + hh * 8;
#pragma unroll
            for (int nj = 0; nj < 8; nj++) {
                const int c = col0 + warp_n * 64 + nj * 8 + tig * 2;
                if (c >= Ntot) continue;
                float v0 = acc[mi][nj][hh * 2 + 0] * alpha;
                float v1 = acc[mi][nj][hh * 2 + 1] * alpha;
                const size_t o = coff + (size_t)r * ldc + c;
                if (EPI == 0) {
                    C[o] = v0 + bias[c];
                    C[o + 1] = v1 + bias[c + 1];
                } else if (EPI == 1) {
                    C[o] = v0;
                    C[o + 1] = v1;
                } else if (EPI == 2) {
                    C[o] = C[o] + v0 + bias[c];
                    C[o + 1] = C[o + 1] + v1 + bias[c + 1];
                } else if (EPI == 3) {
                    bf16 h0, l0, h1, l1;
                    bsplit(v0, h0, l0); bsplit(v1, h1, l1);
                    Ch[o] = h0; Ch[o + 1] = h1;
                    Cl[o] = l0; Cl[o + 1] = l1;
                } else {
                    float g0 = v0 + bias[c], g1 = v1 + bias[c + 1];
                    g0 = 0.5f * g0 * (1.0f + erff(g0 * 0.70710678118654752f));
                    g1 = 0.5f * g1 * (1.0f + erff(g1 * 0.70710678118654752f));
                    bf16 h0, l0, h1, l1;
                    bsplit(g0, h0, l0); bsplit(g1, h1, l1);
                    Ch[o] = h0; Ch[o + 1] = h1;
                    Cl[o] = l0; Cl[o + 1] = l1;
                }
            }
        }
    }
}

// ===================== host-side launch =====================
extern "C" void kernel_launch(void* const* d_in, const int* in_sizes, int n_in,
                              void* d_out, int out_size) {
    const float* hidden = (const float*)d_in[0];
    const float* cosp   = (const float*)d_in[1];
    const float* sinp   = (const float*)d_in[2];
    const float* qkv_w  = (const float*)d_in[3];
    const float* qkv_b  = (const float*)d_in[4];
    const float* proj_w = (const float*)d_in[5];
    const float* proj_b = (const float*)d_in[6];
    const float* ln1_g  = (const float*)d_in[7];
    const float* ln1_b  = (const float*)d_in[8];
    const float* ln2_g  = (const float*)d_in[9];
    const float* ln2_b  = (const float*)d_in[10];
    const float* fc1_w  = (const float*)d_in[11];
    const float* fc1_b  = (const float*)d_in[12];
    const float* fc2_w  = (const float*)d_in[13];
    const float* fc2_b  = (const float*)d_in[14];

    float* x = (float*)d_out;

    float *p_qkv, *p_sc;
    bf16 *p_hh, *p_hl, *p_qh, *p_ql, *p_kh, *p_kl, *p_vth, *p_vtl;
    bf16 *p_ph, *p_pl, *p_ah, *p_al, *p_mh, *p_ml;
    bf16 *wqh, *wql, *wph, *wpl, *w1h, *w1l, *w2h, *w2l;
    cudaGetSymbolAddress((void**)&p_qkv, g_qkv);
    cudaGetSymbolAddress((void**)&p_sc,  g_scores);
    cudaGetSymbolAddress((void**)&p_hh,  g_hh);   cudaGetSymbolAddress((void**)&p_hl, g_hl);
    cudaGetSymbolAddress((void**)&p_qh,  g_qh);   cudaGetSymbolAddress((void**)&p_ql, g_ql);
    cudaGetSymbolAddress((void**)&p_kh,  g_kh);   cudaGetSymbolAddress((void**)&p_kl, g_kl);
    cudaGetSymbolAddress((void**)&p_vth, g_vth);  cudaGetSymbolAddress((void**)&p_vtl, g_vtl);
    cudaGetSymbolAddress((void**)&p_ph,  g_ph);   cudaGetSymbolAddress((void**)&p_pl, g_pl);
    cudaGetSymbolAddress((void**)&p_ah,  g_ah);   cudaGetSymbolAddress((void**)&p_al, g_al);
    cudaGetSymbolAddress((void**)&p_mh,  g_mh);   cudaGetSymbolAddress((void**)&p_ml, g_ml);
    cudaGetSymbolAddress((void**)&wqh, g_wqh);    cudaGetSymbolAddress((void**)&wql, g_wql);
    cudaGetSymbolAddress((void**)&wph, g_wph);    cudaGetSymbolAddress((void**)&wpl, g_wpl);
    cudaGetSymbolAddress((void**)&w1h, g_w1h);    cudaGetSymbolAddress((void**)&w1l, g_w1l);
    cudaGetSymbolAddress((void**)&w2h, g_w2h);    cudaGetSymbolAddress((void**)&w2l, g_w2l);

    cudaFuncSetAttribute((const void*)gemm_mma<0>, cudaFuncAttributeMaxDynamicSharedMemorySize, GEMM_SMEM);
    cudaFuncSetAttribute((const void*)gemm_mma<1>, cudaFuncAttributeMaxDynamicSharedMemorySize, GEMM_SMEM);
    cudaFuncSetAttribute((const void*)gemm_mma<2>, cudaFuncAttributeMaxDynamicSharedMemorySize, GEMM_SMEM);
    cudaFuncSetAttribute((const void*)gemm_mma<3>, cudaFuncAttributeMaxDynamicSharedMemorySize, GEMM_SMEM);
    cudaFuncSetAttribute((const void*)gemm_mma<4>, cudaFuncAttributeMaxDynamicSharedMemorySize, GEMM_SMEM);

    cudaMemcpyAsync(x, hidden, (size_t)S_ * D_ * sizeof(float), cudaMemcpyDeviceToDevice);

    // zero Q/K padding columns once (rope writes only d<80; do it before both layers)
    zero_pad_qk<<<(H_ * S_ * (HDP_ - HD_) + 255) / 256, 256>>>(p_qh, p_ql, p_kh, p_kl);

    for (int l = 0; l < 2; l++) {
        const float* qw = qkv_w + (size_t)l * D_ * NQKV_;
        const float* qb = qkv_b + (size_t)l * NQKV_;
        const float* pw = proj_w + (size_t)l * D_ * D_;
        const float* pb = proj_b + (size_t)l * D_;
        const float* g1 = ln1_g + (size_t)l * D_;
        const float* b1 = ln1_b + (size_t)l * D_;
        const float* g2 = ln2_g + (size_t)l * D_;
        const float* b2 = ln2_b + (size_t)l * D_;
        const float* f1w = fc1_w + (size_t)l * D_ * I_;
        const float* f1b = fc1_b + (size_t)l * I_;
        const float* f2w = fc2_w + (size_t)l * I_ * D_;
        const float* f2b = fc2_b + (size_t)l * D_;

        // weight transpose+split
        wsplit_T_kernel<<<dim3(NQKV_ / 32, D_ / 32), dim3(32, 8)>>>(qw, wqh, wql, D_, NQKV_);
        wsplit_T_kernel<<<dim3(D_ / 32, D_ / 32), dim3(32, 8)>>>(pw, wph, wpl, D_, D_);
        wsplit_T_kernel<<<dim3(I_ / 32, D_ / 32), dim3(32, 8)>>>(f1w, w1h, w1l, D_, I_);
        wsplit_T_kernel<<<dim3(D_ / 32, I_ / 32), dim3(32, 8)>>>(f2w, w2h, w2l, I_, D_);

        // LN1 -> split
        ln_split_kernel<<<S_, 256>>>(x, g1, b1, p_hh, p_hl);

        // qkv = h @ W_qkv + b   (fp32 out)
        gemm_mma<0><<<dim3(NQKV_ / 128, S_ / 128, 1), 256, GEMM_SMEM>>>(
            p_hh, p_hl, wqh, wql, qb, p_qkv, nullptr, nullptr,
            NQKV_, D_, D_, D_, NQKV_, 0, 0, 0, 1.f);

        // RoPE + split + V^T
        rope_split_kernel<<<(S_ * D_ + 255) / 256, 256>>>(p_qkv, cosp, sinp,
                                                          p_qh, p_ql, p_kh, p_kl, p_vth, p_vtl);

        // scores = (Q @ K^T) * SCALE  per head (fp32)
        gemm_mma<1><<<dim3(S_ / 128, S_ / 128, H_), 256, GEMM_SMEM>>>(
            p_qh, p_ql, p_kh, p_kl, nullptr, p_sc, nullptr, nullptr,
            S_, HDP_, HDP_, HDP_, S_,
            (long long)S_ * HDP_, (long long)S_ * HDP_, (long long)S_ * S_, SCALE_);

        // softmax -> split probs
        softmax_kernel<<<H_ * S_, 256>>>(p_sc, p_ph, p_pl);

        // O = P @ V  (bf16 split out into [S,D] with per-head col offset)
        gemm_mma<3><<<dim3(1, S_ / 128, H_), 256, GEMM_SMEM>>>(
            p_ph, p_pl, p_vth, p_vtl, nullptr, nullptr, p_ah, p_al,
            HD_, S_, S_, S_, D_,
            (long long)S_ * S_, (long long)HD_ * S_, (long long)HD_, 1.f);

        // x += O @ W_proj + b
        gemm_mma<2><<<dim3(D_ / 128, S_ / 128, 1), 256, GEMM_SMEM>>>(
            p_ah, p_al, wph, wpl, pb, x, nullptr, nullptr,
            D_, D_, D_, D_, D_, 0, 0, 0, 1.f);

        // LN2 -> split
        ln_split_kernel<<<S_, 256>>>(x, g2, b2, p_hh, p_hl);

        // mlp = gelu(h @ W1 + b)  (bf16 split out)
        gemm_mma<4><<<dim3(I_ / 128, S_ / 128, 1), 256, GEMM_SMEM>>>(
            p_hh, p_hl, w1h, w1l, f1b, nullptr, p_mh, p_ml,
            I_, D_, D_, D_, I_, 0, 0, 0, 1.f);

        // x += mlp @ W2 + b
        gemm_mma<2><<<dim3(D_ / 128, S_ / 128, 1), 256, GEMM_SMEM>>>(
            p_mh, p_ml, w2h, w2l, f2b, x, nullptr, nullptr,
            D_, I_, I_, I_, D_, 0, 0, 0, 1.f);
    }
}

// round 5
// speedup vs baseline: 3.3857x; 1.0824x over previous
#include <cuda_runtime.h>
#include <cuda_bf16.h>
#include <math.h>
#include <stdint.h>

// Problem constants
#define S_ 2048
#define D_ 1280
#define H_ 16
#define HD_ 80
#define HDP_ 96           // padded head dim for score-MMA K (3 chunks of 32)
#define I_ 5120
#define NQKV_ 3840
#define EPS_ 1e-6f
#define SCALE_ 0.11180339887498949f  // 80^-0.5

typedef __nv_bfloat16 bf16;

// ===================== device scratch (no allocation allowed) =====================
__device__ float g_qkv[S_ * NQKV_];                  // qkv proj fp32
__device__ bf16  g_hh[S_ * D_],  g_hl[S_ * D_];      // LN out split
__device__ bf16  g_qh[H_ * S_ * HDP_], g_ql[H_ * S_ * HDP_];
__device__ bf16  g_kh[H_ * S_ * HDP_], g_kl[H_ * S_ * HDP_];
__device__ bf16  g_vth[H_ * HD_ * S_], g_vtl[H_ * HD_ * S_];   // V^T per head
__device__ float g_scores[(size_t)H_ * S_ * S_];     // 268 MB
__device__ bf16  g_ph[(size_t)H_ * S_ * S_], g_pl[(size_t)H_ * S_ * S_];
__device__ bf16  g_ah[S_ * D_],  g_al[S_ * D_];      // attn out split
__device__ bf16  g_mh[S_ * I_],  g_ml[S_ * I_];      // mlp hidden split
__device__ bf16  g_wqh[NQKV_ * D_], g_wql[NQKV_ * D_];
__device__ bf16  g_wph[D_ * D_],    g_wpl[D_ * D_];
__device__ bf16  g_w1h[I_ * D_],    g_w1l[I_ * D_];
__device__ bf16  g_w2h[D_ * I_],    g_w2l[D_ * I_];

__device__ __forceinline__ void bsplit(float v, bf16& h, bf16& l) {
    h = __float2bfloat16(v);
    l = __float2bfloat16(v - __bfloat162float(h));
}

__device__ __forceinline__ uint32_t smem_to_u32(const void* smem_ptr) {
    uint32_t addr;
    asm("{ .reg .u64 tmp; cvta.to.shared.u64 tmp, %1; cvt.u32.u64 %0, tmp; }"
        : "=r"(addr) : "l"(smem_ptr));
    return addr;
}

__device__ __forceinline__ void ldsm4(uint32_t (&r)[4], uint32_t addr) {
    asm volatile("ldmatrix.sync.aligned.m8n8.x4.shared.b16 {%0,%1,%2,%3}, [%4];"
                 : "=r"(r[0]), "=r"(r[1]), "=r"(r[2]), "=r"(r[3]) : "r"(addr));
}

__device__ __forceinline__ void mma16816(float (&d)[4], const uint32_t (&a)[4],
                                         const uint32_t* b) {
    asm volatile(
        "mma.sync.aligned.m16n8k16.row.col.f32.bf16.bf16.f32 "
        "{%0,%1,%2,%3}, {%4,%5,%6,%7}, {%8,%9}, {%0,%1,%2,%3};"
        : "+f"(d[0]), "+f"(d[1]), "+f"(d[2]), "+f"(d[3])
        : "r"(a[0]), "r"(a[1]), "r"(a[2]), "r"(a[3]), "r"(b[0]), "r"(b[1]));
}

__device__ __forceinline__ void cp16(uint32_t dst, const void* src) {
    asm volatile("cp.async.cg.shared.global [%0], [%1], 16;"
                 :: "r"(dst), "l"(src));
}

// ===================== LayerNorm -> bf16 split =====================
__global__ void ln_split_kernel(const float* __restrict__ x,
                                const float* __restrict__ g,
                                const float* __restrict__ b,
                                bf16* __restrict__ oh, bf16* __restrict__ ol) {
    const int row = blockIdx.x;
    const int t = threadIdx.x;
    __shared__ float srow[D_];
    __shared__ float red[256];

    float local = 0.f;
    for (int i = t; i < D_; i += 256) {
        float v = x[(size_t)row * D_ + i];
        srow[i] = v;
        local += v;
    }
    red[t] = local;
    __syncthreads();
    for (int s = 128; s > 0; s >>= 1) { if (t < s) red[t] += red[t + s]; __syncthreads(); }
    const float mean = red[0] * (1.0f / D_);
    __syncthreads();

    local = 0.f;
    for (int i = t; i < D_; i += 256) { float dv = srow[i] - mean; local += dv * dv; }
    red[t] = local;
    __syncthreads();
    for (int s = 128; s > 0; s >>= 1) { if (t < s) red[t] += red[t + s]; __syncthreads(); }
    const float inv = rsqrtf(red[0] * (1.0f / D_) + EPS_);

    for (int i = t; i < D_; i += 256) {
        float v = (srow[i] - mean) * inv * g[i] + b[i];
        bf16 h, l; bsplit(v, h, l);
        oh[(size_t)row * D_ + i] = h;
        ol[(size_t)row * D_ + i] = l;
    }
}

// ===================== weight transpose + split: w[K][N] -> Wt[N][K] =====================
__global__ void wsplit_T_kernel(const float* __restrict__ w,
                                bf16* __restrict__ oh, bf16* __restrict__ ol,
                                int K, int N) {
    __shared__ float tile[32][33];
    int k0 = blockIdx.y * 32, n0 = blockIdx.x * 32;
    int tx = threadIdx.x, ty = threadIdx.y;
#pragma unroll
    for (int j = 0; j < 4; j++)
        tile[ty + j * 8][tx] = w[(size_t)(k0 + ty + j * 8) * N + n0 + tx];
    __syncthreads();
#pragma unroll
    for (int j = 0; j < 4; j++) {
        int n = ty + j * 8;
        float v = tile[tx][n];
        bf16 h, l; bsplit(v, h, l);
        size_t o = (size_t)(n0 + n) * K + k0 + tx;
        oh[o] = h; ol[o] = l;
    }
}

// ===================== RoPE + head split + V transpose (incl. zero pad) =====================
__global__ void rope_split_kernel(const float* __restrict__ qkv,
                                  const float* __restrict__ cosp,
                                  const float* __restrict__ sinp,
                                  bf16* __restrict__ Qh, bf16* __restrict__ Ql,
                                  bf16* __restrict__ Kh, bf16* __restrict__ Kl,
                                  bf16* __restrict__ Vth, bf16* __restrict__ Vtl) {
    int i = blockIdx.x * blockDim.x + threadIdx.x;
    if (i >= S_ * H_ * HDP_) return;
    const int s = i / (H_ * HDP_);
    const int r = i % (H_ * HDP_);
    const int h = r / HDP_;
    const int d = r % HDP_;

    const size_t oq = ((size_t)h * S_ + s) * HDP_ + d;
    if (d >= HD_) {
        const bf16 z = __float2bfloat16(0.f);
        Qh[oq] = z; Ql[oq] = z; Kh[oq] = z; Kl[oq] = z;
        return;
    }

    const float c = cosp[s * HD_ + d];
    const float sn = sinp[s * HD_ + d];
    const size_t base = (size_t)s * NQKV_;

    const int d2 = (d < HD_ / 2) ? d + HD_ / 2 : d - HD_ / 2;
    const float sign = (d < HD_ / 2) ? -1.f : 1.f;

    const float q  = qkv[base + h * HD_ + d];
    const float qp = qkv[base + h * HD_ + d2];
    const float k  = qkv[base + D_ + h * HD_ + d];
    const float kp = qkv[base + D_ + h * HD_ + d2];
    const float v  = qkv[base + 2 * D_ + h * HD_ + d];

    const float rq = q * c + sign * qp * sn;
    const float rk = k * c + sign * kp * sn;

    bf16 hh, ll;
    bsplit(rq, hh, ll); Qh[oq] = hh; Ql[oq] = ll;
    bsplit(rk, hh, ll); Kh[oq] = hh; Kl[oq] = ll;
    const size_t ov = ((size_t)h * HD_ + d) * S_ + s;
    bsplit(v, hh, ll);  Vth[ov] = hh; Vtl[ov] = ll;
}

// ===================== row softmax -> bf16 split probs =====================
__global__ void softmax_kernel(const float* __restrict__ Sc,
                               bf16* __restrict__ Ph, bf16* __restrict__ Pl) {
    const size_t row = blockIdx.x;
    const float* p = Sc + row * S_;
    const int t = threadIdx.x;
    __shared__ float red[256];

    float v[8];
    float m = -1e30f;
#pragma unroll
    for (int i = 0; i < 8; i++) { v[i] = p[t + i * 256]; m = fmaxf(m, v[i]); }
    red[t] = m;
    __syncthreads();
    for (int s = 128; s > 0; s >>= 1) { if (t < s) red[t] = fmaxf(red[t], red[t + s]); __syncthreads(); }
    m = red[0];
    __syncthreads();

    float sum = 0.f;
#pragma unroll
    for (int i = 0; i < 8; i++) { v[i] = expf(v[i] - m); sum += v[i]; }
    red[t] = sum;
    __syncthreads();
    for (int s = 128; s > 0; s >>= 1) { if (t < s) red[t] += red[t + s]; __syncthreads(); }
    const float inv = 1.0f / red[0];
#pragma unroll
    for (int i = 0; i < 8; i++) {
        float pv = v[i] * inv;
        bf16 h, l; bsplit(pv, h, l);
        size_t o = row * S_ + t + i * 256;
        Ph[o] = h; Pl[o] = l;
    }
}

// ===================== 128x256 bf16x3 GEMM, 512 threads, 3-stage =====================
// C[M, N] = alpha * A[M,K] @ B[N,K]^T
// EPI: 0 = C=v+bias  1 = C=v  2 = C+=v+bias  4 = gelu(v+bias) split-store
#define A_T 10240             // 128 rows * 80B pitch
#define B_T 20480             // 256 rows * 80B pitch
#define STAGE_B (2 * A_T + 2 * B_T)   // 61440
#define GEMM2_SMEM (3 * STAGE_B)      // 184320

template <int EPI>
__global__ void __launch_bounds__(512, 1)
gemm_mma2(const bf16* __restrict__ Agh, const bf16* __restrict__ Agl,
          const bf16* __restrict__ Bgh, const bf16* __restrict__ Bgl,
          const float* __restrict__ bias,
          float* __restrict__ C, bf16* __restrict__ Ch, bf16* __restrict__ Cl,
          int K, int lda, int ldb, int ldc,
          long long sA, long long sB, long long sC, float alpha) {
    extern __shared__ __align__(16) char smem[];
    const uint32_t sbase = smem_to_u32(smem);
    const int tid = threadIdx.x;
    const int wid = tid >> 5;
    const int lane = tid & 31;
    const int warp_m = wid & 3;   // 4 x 32 rows
    const int warp_n = wid >> 2;  // 4 x 64 cols
    const int bz = blockIdx.z;

    Agh += (size_t)bz * sA; Agl += (size_t)bz * sA;
    Bgh += (size_t)bz * sB; Bgl += (size_t)bz * sB;
    const size_t coff = (size_t)bz * sC;
    const int row0 = blockIdx.y * 128;
    const int col0 = blockIdx.x * 256;

    const uint32_t a_off = (uint32_t)(((lane & 15) * 40 + (lane >> 4) * 8) * 2);
    const uint32_t b_off = (uint32_t)(((((lane & 7) | ((lane >> 4) << 3)) * 40) +
                                      (((lane >> 3) & 1) * 8)) * 2);

    auto load_chunk = [&](int kc, int stg) {
        const int k0 = kc << 5;
        const uint32_t dbase = sbase + (uint32_t)stg * STAGE_B;
#pragma unroll
        for (int it = 0; it < 2; it++) {
            int e = it * 512 + tid;
            int t = e >> 9;
            int idx = e & 511;
            int row = idx >> 2, c8 = idx & 3;
            const bf16* src = (t ? Agl : Agh) + (size_t)(row0 + row) * lda + k0 + c8 * 8;
            uint32_t dst = dbase + (uint32_t)t * A_T + (uint32_t)(row * 80 + c8 * 16);
            cp16(dst, src);
        }
#pragma unroll
        for (int it = 0; it < 4; it++) {
            int e = it * 512 + tid;
            int t = e >> 10;
            int idx = e & 1023;
            int row = idx >> 2, c8 = idx & 3;
            const bf16* src = (t ? Bgl : Bgh) + (size_t)(col0 + row) * ldb + k0 + c8 * 8;
            uint32_t dst = dbase + 2 * A_T + (uint32_t)t * B_T + (uint32_t)(row * 80 + c8 * 16);
            cp16(dst, src);
        }
    };

    float acc[2][8][4];
#pragma unroll
    for (int mi = 0; mi < 2; mi++)
#pragma unroll
        for (int nj = 0; nj < 8; nj++)
#pragma unroll
            for (int c = 0; c < 4; c++) acc[mi][nj][c] = 0.f;

    const int NC = K >> 5;
    load_chunk(0, 0);
    asm volatile("cp.async.commit_group;" ::: "memory");
    if (1 < NC) load_chunk(1, 1);
    asm volatile("cp.async.commit_group;" ::: "memory");

    int stg = 0;
    for (int kc = 0; kc < NC; kc++) {
        asm volatile("cp.async.wait_group 1;" ::: "memory");
        __syncthreads();
        // prefetch kc+2 into the stage freed by kc-1
        if (kc + 2 < NC) load_chunk(kc + 2, (stg + 2 >= 3) ? stg - 1 : stg + 2);
        asm volatile("cp.async.commit_group;" ::: "memory");

        const uint32_t cbase = sbase + (uint32_t)stg * STAGE_B;
#pragma unroll
        for (int ks = 0; ks < 2; ks++) {
            uint32_t ah[2][4], al[2][4];
#pragma unroll
            for (int mi = 0; mi < 2; mi++) {
                uint32_t ad = cbase + (uint32_t)((warp_m * 32 + mi * 16) * 80 + ks * 32) + a_off;
                ldsm4(ah[mi], ad);
                ldsm4(al[mi], ad + A_T);
            }
#pragma unroll
            for (int ni = 0; ni < 4; ni++) {
                uint32_t bh[4], bl[4];
                uint32_t bd = cbase + 2 * A_T +
                              (uint32_t)((warp_n * 64 + ni * 16) * 80 + ks * 32) + b_off;
                ldsm4(bh, bd);
                ldsm4(bl, bd + B_T);
#pragma unroll
                for (int mi = 0; mi < 2; mi++)
#pragma unroll
                    for (int j = 0; j < 2; j++) {
                        const int nj = ni * 2 + j;
                        mma16816(acc[mi][nj], ah[mi], &bh[j * 2]);
                        mma16816(acc[mi][nj], ah[mi], &bl[j * 2]);
                        mma16816(acc[mi][nj], al[mi], &bh[j * 2]);
                    }
            }
        }
        __syncthreads();
        stg = (stg + 1 >= 3) ? 0 : stg + 1;
    }

    // ---- epilogue ----
    const int gid = lane >> 2, tig = lane & 3;
#pragma unroll
    for (int mi = 0; mi < 2; mi++) {
#pragma unroll
        for (int hh = 0; hh < 2; hh++) {
            const int r = row0 + warp_m * 32 + mi * 16 + gid + hh * 8;
#pragma unroll
            for (int nj = 0; nj < 8; nj++) {
                const int c = col0 + warp_n * 64 + nj * 8 + tig * 2;
                float v0 = acc[mi][nj][hh * 2 + 0] * alpha;
                float v1 = acc[mi][nj][hh * 2 + 1] * alpha;
                const size_t o = coff + (size_t)r * ldc + c;
                if (EPI == 0) {
                    C[o] = v0 + bias[c];
                    C[o + 1] = v1 + bias[c + 1];
                } else if (EPI == 1) {
                    C[o] = v0;
                    C[o + 1] = v1;
                } else if (EPI == 2) {
                    C[o] = C[o] + v0 + bias[c];
                    C[o + 1] = C[o + 1] + v1 + bias[c + 1];
                } else {
                    float g0 = v0 + bias[c], g1 = v1 + bias[c + 1];
                    g0 = 0.5f * g0 * (1.0f + erff(g0 * 0.70710678118654752f));
                    g1 = 0.5f * g1 * (1.0f + erff(g1 * 0.70710678118654752f));
                    bf16 h0, l0, h1, l1;
                    bsplit(g0, h0, l0); bsplit(g1, h1, l1);
                    Ch[o] = h0; Ch[o + 1] = h1;
                    Cl[o] = l0; Cl[o + 1] = l1;
                }
            }
        }
    }
}

// ===================== 128x128 bf16x3 GEMM (PV path, N=80 masked) =====================
#define TILE_B 10240
#define BUF_B (4 * TILE_B)
#define GEMM_SMEM (2 * BUF_B)

template <int EPI>
__global__ void __launch_bounds__(256, 1)
gemm_mma(const bf16* __restrict__ Agh, const bf16* __restrict__ Agl,
         const bf16* __restrict__ Bgh, const bf16* __restrict__ Bgl,
         const float* __restrict__ bias,
         float* __restrict__ C, bf16* __restrict__ Ch, bf16* __restrict__ Cl,
         int Ntot, int K, int lda, int ldb, int ldc,
         long long sA, long long sB, long long sC, float alpha) {
    extern __shared__ __align__(16) char smem[];
    const uint32_t sbase = smem_to_u32(smem);
    const int tid = threadIdx.x;
    const int wid = tid >> 5;
    const int lane = tid & 31;
    const int warp_m = wid & 3;
    const int warp_n = wid >> 2;
    const int bz = blockIdx.z;

    Agh += (size_t)bz * sA; Agl += (size_t)bz * sA;
    Bgh += (size_t)bz * sB; Bgl += (size_t)bz * sB;
    const size_t coff = (size_t)bz * sC;
    const int row0 = blockIdx.y * 128;
    const int col0 = blockIdx.x * 128;

    const uint32_t a_off = (uint32_t)(((lane & 15) * 40 + (lane >> 4) * 8) * 2);
    const uint32_t b_off = (uint32_t)(((((lane & 7) | ((lane >> 4) << 3)) * 40) +
                                      (((lane >> 3) & 1) * 8)) * 2);

    auto load_chunk = [&](int kc, int buf) {
        const int k0 = kc << 5;
        const uint32_t dbase = sbase + (uint32_t)buf * BUF_B;
#pragma unroll
        for (int it = 0; it < 8; it++) {
            int e = it * 256 + tid;
            int t = e >> 9;
            int idx = e & 511;
            int row = idx >> 2;
            int c8 = idx & 3;
            const bf16* src;
            int sz = 16;
            if (t == 0)      src = Agh + (size_t)(row0 + row) * lda + k0 + c8 * 8;
            else if (t == 1) src = Agl + (size_t)(row0 + row) * lda + k0 + c8 * 8;
            else {
                int br = col0 + row;
                if (br >= Ntot) { br = col0; sz = 0; }
                src = (t == 2 ? Bgh : Bgl) + (size_t)br * ldb + k0 + c8 * 8;
            }
            uint32_t dst = dbase + (uint32_t)t * TILE_B + (uint32_t)(row * 80 + c8 * 16);
            asm volatile("cp.async.cg.shared.global [%0], [%1], 16, %2;"
                         :: "r"(dst), "l"(src), "r"(sz));
        }
    };

    float acc[2][8][4];
#pragma unroll
    for (int mi = 0; mi < 2; mi++)
#pragma unroll
        for (int nj = 0; nj < 8; nj++)
#pragma unroll
            for (int c = 0; c < 4; c++) acc[mi][nj][c] = 0.f;

    const int NC = K >> 5;
    load_chunk(0, 0);
    asm volatile("cp.async.commit_group;" ::: "memory");

    for (int kc = 0; kc < NC; kc++) {
        const int buf = kc & 1;
        if (kc + 1 < NC) {
            load_chunk(kc + 1, buf ^ 1);
            asm volatile("cp.async.commit_group;" ::: "memory");
            asm volatile("cp.async.wait_group 1;" ::: "memory");
        } else {
            asm volatile("cp.async.wait_group 0;" ::: "memory");
        }
        __syncthreads();

        const uint32_t bofs = sbase + (uint32_t)buf * BUF_B;
#pragma unroll
        for (int ks = 0; ks < 2; ks++) {
            uint32_t ah[2][4], al[2][4], bh[4][4], bl[4][4];
#pragma unroll
            for (int mi = 0; mi < 2; mi++) {
                uint32_t ad = bofs + (uint32_t)((warp_m * 32 + mi * 16) * 80 + ks * 32) + a_off;
                ldsm4(ah[mi], ad);
                ldsm4(al[mi], ad + TILE_B);
            }
#pragma unroll
            for (int ni = 0; ni < 4; ni++) {
                uint32_t bd = bofs + 2 * TILE_B +
                              (uint32_t)((warp_n * 64 + ni * 16) * 80 + ks * 32) + b_off;
                ldsm4(bh[ni], bd);
                ldsm4(bl[ni], bd + TILE_B);
            }
#pragma unroll
            for (int mi = 0; mi < 2; mi++)
#pragma unroll
                for (int nj = 0; nj < 8; nj++) {
                    const uint32_t* bhp = &bh[nj >> 1][(nj & 1) * 2];
                    const uint32_t* blp = &bl[nj >> 1][(nj & 1) * 2];
                    mma16816(acc[mi][nj], ah[mi], bhp);
                    mma16816(acc[mi][nj], ah[mi], blp);
                    mma16816(acc[mi][nj], al[mi], bhp);
                }
        }
        __syncthreads();
    }

    const int gid = lane >> 2, tig = lane & 3;
#pragma unroll
    for (int mi = 0; mi < 2; mi++) {
#pragma unroll
        for (int hh = 0; hh < 2; hh++) {
            const int r = row0 + warp_m * 32 + mi * 16 + gid + hh * 8;
#pragma unroll
            for (int nj = 0; nj < 8; nj++) {
                const int c = col0 + warp_n * 64 + nj * 8 + tig * 2;
                if (c >= Ntot) continue;
                float v0 = acc[mi][nj][hh * 2 + 0] * alpha;
                float v1 = acc[mi][nj][hh * 2 + 1] * alpha;
                const size_t o = coff + (size_t)r * ldc + c;
                if (EPI == 3) {
                    bf16 h0, l0, h1, l1;
                    bsplit(v0, h0, l0); bsplit(v1, h1, l1);
                    Ch[o] = h0; Ch[o + 1] = h1;
                    Cl[o] = l0; Cl[o + 1] = l1;
                }
            }
        }
    }
}

// ===================== host-side launch =====================
extern "C" void kernel_launch(void* const* d_in, const int* in_sizes, int n_in,
                              void* d_out, int out_size) {
    const float* hidden = (const float*)d_in[0];
    const float* cosp   = (const float*)d_in[1];
    const float* sinp   = (const float*)d_in[2];
    const float* qkv_w  = (const float*)d_in[3];
    const float* qkv_b  = (const float*)d_in[4];
    const float* proj_w = (const float*)d_in[5];
    const float* proj_b = (const float*)d_in[6];
    const float* ln1_g  = (const float*)d_in[7];
    const float* ln1_b  = (const float*)d_in[8];
    const float* ln2_g  = (const float*)d_in[9];
    const float* ln2_b  = (const float*)d_in[10];
    const float* fc1_w  = (const float*)d_in[11];
    const float* fc1_b  = (const float*)d_in[12];
    const float* fc2_w  = (const float*)d_in[13];
    const float* fc2_b  = (const float*)d_in[14];

    float* x = (float*)d_out;

    float *p_qkv, *p_sc;
    bf16 *p_hh, *p_hl, *p_qh, *p_ql, *p_kh, *p_kl, *p_vth, *p_vtl;
    bf16 *p_ph, *p_pl, *p_ah, *p_al, *p_mh, *p_ml;
    bf16 *wqh, *wql, *wph, *wpl, *w1h, *w1l, *w2h, *w2l;
    cudaGetSymbolAddress((void**)&p_qkv, g_qkv);
    cudaGetSymbolAddress((void**)&p_sc,  g_scores);
    cudaGetSymbolAddress((void**)&p_hh,  g_hh);   cudaGetSymbolAddress((void**)&p_hl, g_hl);
    cudaGetSymbolAddress((void**)&p_qh,  g_qh);   cudaGetSymbolAddress((void**)&p_ql, g_ql);
    cudaGetSymbolAddress((void**)&p_kh,  g_kh);   cudaGetSymbolAddress((void**)&p_kl, g_kl);
    cudaGetSymbolAddress((void**)&p_vth, g_vth);  cudaGetSymbolAddress((void**)&p_vtl, g_vtl);
    cudaGetSymbolAddress((void**)&p_ph,  g_ph);   cudaGetSymbolAddress((void**)&p_pl, g_pl);
    cudaGetSymbolAddress((void**)&p_ah,  g_ah);   cudaGetSymbolAddress((void**)&p_al, g_al);
    cudaGetSymbolAddress((void**)&p_mh,  g_mh);   cudaGetSymbolAddress((void**)&p_ml, g_ml);
    cudaGetSymbolAddress((void**)&wqh, g_wqh);    cudaGetSymbolAddress((void**)&wql, g_wql);
    cudaGetSymbolAddress((void**)&wph, g_wph);    cudaGetSymbolAddress((void**)&wpl, g_wpl);
    cudaGetSymbolAddress((void**)&w1h, g_w1h);    cudaGetSymbolAddress((void**)&w1l, g_w1l);
    cudaGetSymbolAddress((void**)&w2h, g_w2h);    cudaGetSymbolAddress((void**)&w2l, g_w2l);

    cudaFuncSetAttribute((const void*)gemm_mma2<0>, cudaFuncAttributeMaxDynamicSharedMemorySize, GEMM2_SMEM);
    cudaFuncSetAttribute((const void*)gemm_mma2<1>, cudaFuncAttributeMaxDynamicSharedMemorySize, GEMM2_SMEM);
    cudaFuncSetAttribute((const void*)gemm_mma2<2>, cudaFuncAttributeMaxDynamicSharedMemorySize, GEMM2_SMEM);
    cudaFuncSetAttribute((const void*)gemm_mma2<4>, cudaFuncAttributeMaxDynamicSharedMemorySize, GEMM2_SMEM);
    cudaFuncSetAttribute((const void*)gemm_mma<3>,  cudaFuncAttributeMaxDynamicSharedMemorySize, GEMM_SMEM);

    cudaMemcpyAsync(x, hidden, (size_t)S_ * D_ * sizeof(float), cudaMemcpyDeviceToDevice);

    for (int l = 0; l < 2; l++) {
        const float* qw = qkv_w + (size_t)l * D_ * NQKV_;
        const float* qb = qkv_b + (size_t)l * NQKV_;
        const float* pw = proj_w + (size_t)l * D_ * D_;
        const float* pb = proj_b + (size_t)l * D_;
        const float* g1 = ln1_g + (size_t)l * D_;
        const float* b1 = ln1_b + (size_t)l * D_;
        const float* g2 = ln2_g + (size_t)l * D_;
        const float* b2 = ln2_b + (size_t)l * D_;
        const float* f1w = fc1_w + (size_t)l * D_ * I_;
        const float* f1b = fc1_b + (size_t)l * I_;
        const float* f2w = fc2_w + (size_t)l * I_ * D_;
        const float* f2b = fc2_b + (size_t)l * D_;

        // weight transpose+split
        wsplit_T_kernel<<<dim3(NQKV_ / 32, D_ / 32), dim3(32, 8)>>>(qw, wqh, wql, D_, NQKV_);
        wsplit_T_kernel<<<dim3(D_ / 32, D_ / 32), dim3(32, 8)>>>(pw, wph, wpl, D_, D_);
        wsplit_T_kernel<<<dim3(I_ / 32, D_ / 32), dim3(32, 8)>>>(f1w, w1h, w1l, D_, I_);
        wsplit_T_kernel<<<dim3(D_ / 32, I_ / 32), dim3(32, 8)>>>(f2w, w2h, w2l, I_, D_);

        // LN1 -> split
        ln_split_kernel<<<S_, 256>>>(x, g1, b1, p_hh, p_hl);

        // qkv = h @ W_qkv + b   (fp32 out)
        gemm_mma2<0><<<dim3(NQKV_ / 256, S_ / 128, 1), 512, GEMM2_SMEM>>>(
            p_hh, p_hl, wqh, wql, qb, p_qkv, nullptr, nullptr,
            D_, D_, D_, NQKV_, 0, 0, 0, 1.f);

        // RoPE + split + V^T (+zero pad)
        rope_split_kernel<<<(S_ * H_ * HDP_ + 255) / 256, 256>>>(
            p_qkv, cosp, sinp, p_qh, p_ql, p_kh, p_kl, p_vth, p_vtl);

        // scores = (Q @ K^T) * SCALE  per head (fp32), K padded to 96
        gemm_mma2<1><<<dim3(S_ / 256, S_ / 128, H_), 512, GEMM2_SMEM>>>(
            p_qh, p_ql, p_kh, p_kl, nullptr, p_sc, nullptr, nullptr,
            HDP_, HDP_, HDP_, S_,
            (long long)S_ * HDP_, (long long)S_ * HDP_, (long long)S_ * S_, SCALE_);

        // softmax -> split probs
        softmax_kernel<<<H_ * S_, 256>>>(p_sc, p_ph, p_pl);

        // O = P @ V  (bf16 split out into [S,D] with per-head col offset)
        gemm_mma<3><<<dim3(1, S_ / 128, H_), 256, GEMM_SMEM>>>(
            p_ph, p_pl, p_vth, p_vtl, nullptr, nullptr, p_ah, p_al,
            HD_, S_, S_, S_, D_,
            (long long)S_ * S_, (long long)HD_ * S_, (long long)HD_, 1.f);

        // x += O @ W_proj + b
        gemm_mma2<2><<<dim3(D_ / 256, S_ / 128, 1), 512, GEMM2_SMEM>>>(
            p_ah, p_al, wph, wpl, pb, x, nullptr, nullptr,
            D_, D_, D_, D_, 0, 0, 0, 1.f);

        // LN2 -> split
        ln_split_kernel<<<S_, 256>>>(x, g2, b2, p_hh, p_hl);

        // mlp = gelu(h @ W1 + b)  (bf16 split out)
        gemm_mma2<4><<<dim3(I_ / 256, S_ / 128, 1), 512, GEMM2_SMEM>>>(
            p_hh, p_hl, w1h, w1l, f1b, nullptr, p_mh, p_ml,
            D_, D_, D_, I_, 0, 0, 0, 1.f);

        // x += mlp @ W2 + b
        gemm_mma2<2><<<dim3(D_ / 256, S_ / 128, 1), 512, GEMM2_SMEM>>>(
            p_mh, p_ml, w2h, w2l, f2b, x, nullptr, nullptr,
            I_, I_, I_, D_, 0, 0, 0, 1.f);
    }
}

// round 6
// speedup vs baseline: 3.3886x; 1.0008x over previous
#include <cuda_runtime.h>
#include <cuda_bf16.h>
#include <math.h>
#include <stdint.h>

// Problem constants
#define S_ 2048
#define D_ 1280
#define H_ 16
#define HD_ 80
#define HDP_ 96           // padded head dim for score-MMA K (3 chunks of 32)
#define I_ 5120
#define NQKV_ 3840
#define EPS_ 1e-6f
#define SCALE_ 0.11180339887498949f  // 80^-0.5

typedef __nv_bfloat16 bf16;

// ===================== device scratch (no allocation allowed) =====================
__device__ float g_qkv[S_ * NQKV_];                  // qkv proj fp32
__device__ bf16  g_hh[S_ * D_],  g_hl[S_ * D_];      // LN out split
__device__ bf16  g_qh[H_ * S_ * HDP_], g_ql[H_ * S_ * HDP_];
__device__ bf16  g_kh[H_ * S_ * HDP_], g_kl[H_ * S_ * HDP_];
__device__ bf16  g_vth[H_ * HD_ * S_], g_vtl[H_ * HD_ * S_];   // V^T per head
__device__ float g_scores[(size_t)H_ * S_ * S_];     // 268 MB
__device__ bf16  g_ph[(size_t)H_ * S_ * S_], g_pl[(size_t)H_ * S_ * S_];
__device__ bf16  g_ah[S_ * D_],  g_al[S_ * D_];      // attn out split
__device__ bf16  g_mh[S_ * I_],  g_ml[S_ * I_];      // mlp hidden split
__device__ bf16  g_wqh[NQKV_ * D_], g_wql[NQKV_ * D_];
__device__ bf16  g_wph[D_ * D_],    g_wpl[D_ * D_];
__device__ bf16  g_w1h[I_ * D_],    g_w1l[I_ * D_];
__device__ bf16  g_w2h[D_ * I_],    g_w2l[D_ * I_];

__device__ __forceinline__ void bsplit(float v, bf16& h, bf16& l) {
    h = __float2bfloat16(v);
    l = __float2bfloat16(v - __bfloat162float(h));
}

__device__ __forceinline__ uint32_t smem_to_u32(const void* smem_ptr) {
    uint32_t addr;
    asm("{ .reg .u64 tmp; cvta.to.shared.u64 tmp, %1; cvt.u32.u64 %0, tmp; }"
        : "=r"(addr) : "l"(smem_ptr));
    return addr;
}

__device__ __forceinline__ void ldsm4(uint32_t (&r)[4], uint32_t addr) {
    asm volatile("ldmatrix.sync.aligned.m8n8.x4.shared.b16 {%0,%1,%2,%3}, [%4];"
                 : "=r"(r[0]), "=r"(r[1]), "=r"(r[2]), "=r"(r[3]) : "r"(addr));
}

__device__ __forceinline__ void mma16816(float (&d)[4], const uint32_t (&a)[4],
                                         const uint32_t* b) {
    asm volatile(
        "mma.sync.aligned.m16n8k16.row.col.f32.bf16.bf16.f32 "
        "{%0,%1,%2,%3}, {%4,%5,%6,%7}, {%8,%9}, {%0,%1,%2,%3};"
        : "+f"(d[0]), "+f"(d[1]), "+f"(d[2]), "+f"(d[3])
        : "r"(a[0]), "r"(a[1]), "r"(a[2]), "r"(a[3]), "r"(b[0]), "r"(b[1]));
}

__device__ __forceinline__ void cp16(uint32_t dst, const void* src) {
    asm volatile("cp.async.cg.shared.global [%0], [%1], 16;"
                 :: "r"(dst), "l"(src));
}

// ===================== LayerNorm -> bf16 split =====================
__global__ void ln_split_kernel(const float* __restrict__ x,
                                const float* __restrict__ g,
                                const float* __restrict__ b,
                                bf16* __restrict__ oh, bf16* __restrict__ ol) {
    const int row = blockIdx.x;
    const int t = threadIdx.x;
    __shared__ float srow[D_];
    __shared__ float red[256];

    float local = 0.f;
    for (int i = t; i < D_; i += 256) {
        float v = x[(size_t)row * D_ + i];
        srow[i] = v;
        local += v;
    }
    red[t] = local;
    __syncthreads();
    for (int s = 128; s > 0; s >>= 1) { if (t < s) red[t] += red[t + s]; __syncthreads(); }
    const float mean = red[0] * (1.0f / D_);
    __syncthreads();

    local = 0.f;
    for (int i = t; i < D_; i += 256) { float dv = srow[i] - mean; local += dv * dv; }
    red[t] = local;
    __syncthreads();
    for (int s = 128; s > 0; s >>= 1) { if (t < s) red[t] += red[t + s]; __syncthreads(); }
    const float inv = rsqrtf(red[0] * (1.0f / D_) + EPS_);

    for (int i = t; i < D_; i += 256) {
        float v = (srow[i] - mean) * inv * g[i] + b[i];
        bf16 h, l; bsplit(v, h, l);
        oh[(size_t)row * D_ + i] = h;
        ol[(size_t)row * D_ + i] = l;
    }
}

// ===================== weight transpose + split: w[K][N] -> Wt[N][K] =====================
__global__ void wsplit_T_kernel(const float* __restrict__ w,
                                bf16* __restrict__ oh, bf16* __restrict__ ol,
                                int K, int N) {
    __shared__ float tile[32][33];
    int k0 = blockIdx.y * 32, n0 = blockIdx.x * 32;
    int tx = threadIdx.x, ty = threadIdx.y;
#pragma unroll
    for (int j = 0; j < 4; j++)
        tile[ty + j * 8][tx] = w[(size_t)(k0 + ty + j * 8) * N + n0 + tx];
    __syncthreads();
#pragma unroll
    for (int j = 0; j < 4; j++) {
        int n = ty + j * 8;
        float v = tile[tx][n];
        bf16 h, l; bsplit(v, h, l);
        size_t o = (size_t)(n0 + n) * K + k0 + tx;
        oh[o] = h; ol[o] = l;
    }
}

// ===================== RoPE + head split + V transpose (incl. zero pad) =====================
__global__ void rope_split_kernel(const float* __restrict__ qkv,
                                  const float* __restrict__ cosp,
                                  const float* __restrict__ sinp,
                                  bf16* __restrict__ Qh, bf16* __restrict__ Ql,
                                  bf16* __restrict__ Kh, bf16* __restrict__ Kl,
                                  bf16* __restrict__ Vth, bf16* __restrict__ Vtl) {
    int i = blockIdx.x * blockDim.x + threadIdx.x;
    if (i >= S_ * H_ * HDP_) return;
    const int s = i / (H_ * HDP_);
    const int r = i % (H_ * HDP_);
    const int h = r / HDP_;
    const int d = r % HDP_;

    const size_t oq = ((size_t)h * S_ + s) * HDP_ + d;
    if (d >= HD_) {
        const bf16 z = __float2bfloat16(0.f);
        Qh[oq] = z; Ql[oq] = z; Kh[oq] = z; Kl[oq] = z;
        return;
    }

    const float c = cosp[s * HD_ + d];
    const float sn = sinp[s * HD_ + d];
    const size_t base = (size_t)s * NQKV_;

    const int d2 = (d < HD_ / 2) ? d + HD_ / 2 : d - HD_ / 2;
    const float sign = (d < HD_ / 2) ? -1.f : 1.f;

    const float q  = qkv[base + h * HD_ + d];
    const float qp = qkv[base + h * HD_ + d2];
    const float k  = qkv[base + D_ + h * HD_ + d];
    const float kp = qkv[base + D_ + h * HD_ + d2];
    const float v  = qkv[base + 2 * D_ + h * HD_ + d];

    const float rq = q * c + sign * qp * sn;
    const float rk = k * c + sign * kp * sn;

    bf16 hh, ll;
    bsplit(rq, hh, ll); Qh[oq] = hh; Ql[oq] = ll;
    bsplit(rk, hh, ll); Kh[oq] = hh; Kl[oq] = ll;
    const size_t ov = ((size_t)h * HD_ + d) * S_ + s;
    bsplit(v, hh, ll);  Vth[ov] = hh; Vtl[ov] = ll;
}

// ===================== row softmax -> bf16 split probs =====================
__global__ void softmax_kernel(const float* __restrict__ Sc,
                               bf16* __restrict__ Ph, bf16* __restrict__ Pl) {
    const size_t row = blockIdx.x;
    const float* p = Sc + row * S_;
    const int t = threadIdx.x;
    __shared__ float red[256];

    float v[8];
    float m = -1e30f;
#pragma unroll
    for (int i = 0; i < 8; i++) { v[i] = p[t + i * 256]; m = fmaxf(m, v[i]); }
    red[t] = m;
    __syncthreads();
    for (int s = 128; s > 0; s >>= 1) { if (t < s) red[t] = fmaxf(red[t], red[t + s]); __syncthreads(); }
    m = red[0];
    __syncthreads();

    float sum = 0.f;
#pragma unroll
    for (int i = 0; i < 8; i++) { v[i] = expf(v[i] - m); sum += v[i]; }
    red[t] = sum;
    __syncthreads();
    for (int s = 128; s > 0; s >>= 1) { if (t < s) red[t] += red[t + s]; __syncthreads(); }
    const float inv = 1.0f / red[0];
#pragma unroll
    for (int i = 0; i < 8; i++) {
        float pv = v[i] * inv;
        bf16 h, l; bsplit(pv, h, l);
        size_t o = row * S_ + t + i * 256;
        Ph[o] = h; Pl[o] = l;
    }
}

// ===================== 128x256 bf16x3 GEMM, 512 threads, 3-stage =====================
// C[M, N] = alpha * A[M,K] @ B[N,K]^T
// EPI: 0 = C=v+bias  1 = C=v  2 = C+=v+bias  4 = gelu(v+bias) split-store
#define A_T 10240             // 128 rows * 80B pitch
#define B_T 20480             // 256 rows * 80B pitch
#define STAGE_B (2 * A_T + 2 * B_T)   // 61440
#define GEMM2_SMEM (3 * STAGE_B)      // 184320

template <int EPI>
__global__ void __launch_bounds__(512, 1)
gemm_mma2(const bf16* __restrict__ Agh, const bf16* __restrict__ Agl,
          const bf16* __restrict__ Bgh, const bf16* __restrict__ Bgl,
          const float* __restrict__ bias,
          float* __restrict__ C, bf16* __restrict__ Ch, bf16* __restrict__ Cl,
          int K, int lda, int ldb, int ldc,
          long long sA, long long sB, long long sC, float alpha) {
    extern __shared__ __align__(16) char smem[];
    const uint32_t sbase = smem_to_u32(smem);
    const int tid = threadIdx.x;
    const int wid = tid >> 5;
    const int lane = tid & 31;
    const int warp_m = wid & 3;   // 4 x 32 rows
    const int warp_n = wid >> 2;  // 4 x 64 cols
    const int bz = blockIdx.z;

    Agh += (size_t)bz * sA; Agl += (size_t)bz * sA;
    Bgh += (size_t)bz * sB; Bgl += (size_t)bz * sB;
    const size_t coff = (size_t)bz * sC;
    const int row0 = blockIdx.y * 128;
    const int col0 = blockIdx.x * 256;

    const uint32_t a_off = (uint32_t)(((lane & 15) * 40 + (lane >> 4) * 8) * 2);
    const uint32_t b_off = (uint32_t)(((((lane & 7) | ((lane >> 4) << 3)) * 40) +
                                      (((lane >> 3) & 1) * 8)) * 2);

    auto load_chunk = [&](int kc, int stg) {
        const int k0 = kc << 5;
        const uint32_t dbase = sbase + (uint32_t)stg * STAGE_B;
#pragma unroll
        for (int it = 0; it < 2; it++) {
            int e = it * 512 + tid;
            int t = e >> 9;
            int idx = e & 511;
            int row = idx >> 2, c8 = idx & 3;
            const bf16* src = (t ? Agl : Agh) + (size_t)(row0 + row) * lda + k0 + c8 * 8;
            uint32_t dst = dbase + (uint32_t)t * A_T + (uint32_t)(row * 80 + c8 * 16);
            cp16(dst, src);
        }
#pragma unroll
        for (int it = 0; it < 4; it++) {
            int e = it * 512 + tid;
            int t = e >> 10;
            int idx = e & 1023;
            int row = idx >> 2, c8 = idx & 3;
            const bf16* src = (t ? Bgl : Bgh) + (size_t)(col0 + row) * ldb + k0 + c8 * 8;
            uint32_t dst = dbase + 2 * A_T + (uint32_t)t * B_T + (uint32_t)(row * 80 + c8 * 16);
            cp16(dst, src);
        }
    };

    float acc[2][8][4];
#pragma unroll
    for (int mi = 0; mi < 2; mi++)
#pragma unroll
        for (int nj = 0; nj < 8; nj++)
#pragma unroll
            for (int c = 0; c < 4; c++) acc[mi][nj][c] = 0.f;

    const int NC = K >> 5;
    load_chunk(0, 0);
    asm volatile("cp.async.commit_group;" ::: "memory");
    if (1 < NC) load_chunk(1, 1);
    asm volatile("cp.async.commit_group;" ::: "memory");

    int stg = 0;
    for (int kc = 0; kc < NC; kc++) {
        asm volatile("cp.async.wait_group 1;" ::: "memory");
        __syncthreads();
        // prefetch kc+2 into the stage freed by kc-1
        if (kc + 2 < NC) load_chunk(kc + 2, (stg + 2 >= 3) ? stg - 1 : stg + 2);
        asm volatile("cp.async.commit_group;" ::: "memory");

        const uint32_t cbase = sbase + (uint32_t)stg * STAGE_B;
#pragma unroll
        for (int ks = 0; ks < 2; ks++) {
            uint32_t ah[2][4], al[2][4];
#pragma unroll
            for (int mi = 0; mi < 2; mi++) {
                uint32_t ad = cbase + (uint32_t)((warp_m * 32 + mi * 16) * 80 + ks * 32) + a_off;
                ldsm4(ah[mi], ad);
                ldsm4(al[mi], ad + A_T);
            }
#pragma unroll
            for (int ni = 0; ni < 4; ni++) {
                uint32_t bh[4], bl[4];
                uint32_t bd = cbase + 2 * A_T +
                              (uint32_t)((warp_n * 64 + ni * 16) * 80 + ks * 32) + b_off;
                ldsm4(bh, bd);
                ldsm4(bl, bd + B_T);
#pragma unroll
                for (int mi = 0; mi < 2; mi++)
#pragma unroll
                    for (int j = 0; j < 2; j++) {
                        const int nj = ni * 2 + j;
                        mma16816(acc[mi][nj], ah[mi], &bh[j * 2]);
                        mma16816(acc[mi][nj], ah[mi], &bl[j * 2]);
                        mma16816(acc[mi][nj], al[mi], &bh[j * 2]);
                    }
            }
        }
        __syncthreads();
        stg = (stg + 1 >= 3) ? 0 : stg + 1;
    }

    // ---- epilogue ----
    const int gid = lane >> 2, tig = lane & 3;
#pragma unroll
    for (int mi = 0; mi < 2; mi++) {
#pragma unroll
        for (int hh = 0; hh < 2; hh++) {
            const int r = row0 + warp_m * 32 + mi * 16 + gid + hh * 8;
#pragma unroll
            for (int nj = 0; nj < 8; nj++) {
                const int c = col0 + warp_n * 64 + nj * 8 + tig * 2;
                float v0 = acc[mi][nj][hh * 2 + 0] * alpha;
                float v1 = acc[mi][nj][hh * 2 + 1] * alpha;
                const size_t o = coff + (size_t)r * ldc + c;
                if (EPI == 0) {
                    C[o] = v0 + bias[c];
                    C[o + 1] = v1 + bias[c + 1];
                } else if (EPI == 1) {
                    C[o] = v0;
                    C[o + 1] = v1;
                } else if (EPI == 2) {
                    C[o] = C[o] + v0 + bias[c];
                    C[o + 1] = C[o + 1] + v1 + bias[c + 1];
                } else {
                    float g0 = v0 + bias[c], g1 = v1 + bias[c + 1];
                    g0 = 0.5f * g0 * (1.0f + erff(g0 * 0.70710678118654752f));
                    g1 = 0.5f * g1 * (1.0f + erff(g1 * 0.70710678118654752f));
                    bf16 h0, l0, h1, l1;
                    bsplit(g0, h0, l0); bsplit(g1, h1, l1);
                    Ch[o] = h0; Ch[o + 1] = h1;
                    Cl[o] = l0; Cl[o + 1] = l1;
                }
            }
        }
    }
}

// ===================== 128x128 bf16x3 GEMM (PV path, N=80 masked) =====================
#define TILE_B 10240
#define BUF_B (4 * TILE_B)
#define GEMM_SMEM (2 * BUF_B)

template <int EPI>
__global__ void __launch_bounds__(256, 1)
gemm_mma(const bf16* __restrict__ Agh, const bf16* __restrict__ Agl,
         const bf16* __restrict__ Bgh, const bf16* __restrict__ Bgl,
         const float* __restrict__ bias,
         float* __restrict__ C, bf16* __restrict__ Ch, bf16* __restrict__ Cl,
         int Ntot, int K, int lda, int ldb, int ldc,
         long long sA, long long sB, long long sC, float alpha) {
    extern __shared__ __align__(16) char smem[];
    const uint32_t sbase = smem_to_u32(smem);
    const int tid = threadIdx.x;
    const int wid = tid >> 5;
    const int lane = tid & 31;
    const int warp_m = wid & 3;
    const int warp_n = wid >> 2;
    const int bz = blockIdx.z;

    Agh += (size_t)bz * sA; Agl += (size_t)bz * sA;
    Bgh += (size_t)bz * sB; Bgl += (size_t)bz * sB;
    const size_t coff = (size_t)bz * sC;
    const int row0 = blockIdx.y * 128;
    const int col0 = blockIdx.x * 128;

    const uint32_t a_off = (uint32_t)(((lane & 15) * 40 + (lane >> 4) * 8) * 2);
    const uint32_t b_off = (uint32_t)(((((lane & 7) | ((lane >> 4) << 3)) * 40) +
                                      (((lane >> 3) & 1) * 8)) * 2);

    auto load_chunk = [&](int kc, int buf) {
        const int k0 = kc << 5;
        const uint32_t dbase = sbase + (uint32_t)buf * BUF_B;
#pragma unroll
        for (int it = 0; it < 8; it++) {
            int e = it * 256 + tid;
            int t = e >> 9;
            int idx = e & 511;
            int row = idx >> 2;
            int c8 = idx & 3;
            const bf16* src;
            int sz = 16;
            if (t == 0)      src = Agh + (size_t)(row0 + row) * lda + k0 + c8 * 8;
            else if (t == 1) src = Agl + (size_t)(row0 + row) * lda + k0 + c8 * 8;
            else {
                int br = col0 + row;
                if (br >= Ntot) { br = col0; sz = 0; }
                src = (t == 2 ? Bgh : Bgl) + (size_t)br * ldb + k0 + c8 * 8;
            }
            uint32_t dst = dbase + (uint32_t)t * TILE_B + (uint32_t)(row * 80 + c8 * 16);
            asm volatile("cp.async.cg.shared.global [%0], [%1], 16, %2;"
                         :: "r"(dst), "l"(src), "r"(sz));
        }
    };

    float acc[2][8][4];
#pragma unroll
    for (int mi = 0; mi < 2; mi++)
#pragma unroll
        for (int nj = 0; nj < 8; nj++)
#pragma unroll
            for (int c = 0; c < 4; c++) acc[mi][nj][c] = 0.f;

    const int NC = K >> 5;
    load_chunk(0, 0);
    asm volatile("cp.async.commit_group;" ::: "memory");

    for (int kc = 0; kc < NC; kc++) {
        const int buf = kc & 1;
        if (kc + 1 < NC) {
            load_chunk(kc + 1, buf ^ 1);
            asm volatile("cp.async.commit_group;" ::: "memory");
            asm volatile("cp.async.wait_group 1;" ::: "memory");
        } else {
            asm volatile("cp.async.wait_group 0;" ::: "memory");
        }
        __syncthreads();

        const uint32_t bofs = sbase + (uint32_t)buf * BUF_B;
#pragma unroll
        for (int ks = 0; ks < 2; ks++) {
            uint32_t ah[2][4], al[2][4], bh[4][4], bl[4][4];
#pragma unroll
            for (int mi = 0; mi < 2; mi++) {
                uint32_t ad = bofs + (uint32_t)((warp_m * 32 + mi * 16) * 80 + ks * 32) + a_off;
                ldsm4(ah[mi], ad);
                ldsm4(al[mi], ad + TILE_B);
            }
#pragma unroll
            for (int ni = 0; ni < 4; ni++) {
                uint32_t bd = bofs + 2 * TILE_B +
                              (uint32_t)((warp_n * 64 + ni * 16) * 80 + ks * 32) + b_off;
                ldsm4(bh[ni], bd);
                ldsm4(bl[ni], bd + TILE_B);
            }
#pragma unroll
            for (int mi = 0; mi < 2; mi++)
#pragma unroll
                for (int nj = 0; nj < 8; nj++) {
                    const uint32_t* bhp = &bh[nj >> 1][(nj & 1) * 2];
                    const uint32_t* blp = &bl[nj >> 1][(nj & 1) * 2];
                    mma16816(acc[mi][nj], ah[mi], bhp);
                    mma16816(acc[mi][nj], ah[mi], blp);
                    mma16816(acc[mi][nj], al[mi], bhp);
                }
        }
        __syncthreads();
    }

    const int gid = lane >> 2, tig = lane & 3;
#pragma unroll
    for (int mi = 0; mi < 2; mi++) {
#pragma unroll
        for (int hh = 0; hh < 2; hh++) {
            const int r = row0 + warp_m * 32 + mi * 16 + gid + hh * 8;
#pragma unroll
            for (int nj = 0; nj < 8; nj++) {
                const int c = col0 + warp_n * 64 + nj * 8 + tig * 2;
                if (c >= Ntot) continue;
                float v0 = acc[mi][nj][hh * 2 + 0] * alpha;
                float v1 = acc[mi][nj][hh * 2 + 1] * alpha;
                const size_t o = coff + (size_t)r * ldc + c;
                if (EPI == 3) {
                    bf16 h0, l0, h1, l1;
                    bsplit(v0, h0, l0); bsplit(v1, h1, l1);
                    Ch[o] = h0; Ch[o + 1] = h1;
                    Cl[o] = l0; Cl[o + 1] = l1;
                }
            }
        }
    }
}

// ===================== host-side launch =====================
extern "C" void kernel_launch(void* const* d_in, const int* in_sizes, int n_in,
                              void* d_out, int out_size) {
    const float* hidden = (const float*)d_in[0];
    const float* cosp   = (const float*)d_in[1];
    const float* sinp   = (const float*)d_in[2];
    const float* qkv_w  = (const float*)d_in[3];
    const float* qkv_b  = (const float*)d_in[4];
    const float* proj_w = (const float*)d_in[5];
    const float* proj_b = (const float*)d_in[6];
    const float* ln1_g  = (const float*)d_in[7];
    const float* ln1_b  = (const float*)d_in[8];
    const float* ln2_g  = (const float*)d_in[9];
    const float* ln2_b  = (const float*)d_in[10];
    const float* fc1_w  = (const float*)d_in[11];
    const float* fc1_b  = (const float*)d_in[12];
    const float* fc2_w  = (const float*)d_in[13];
    const float* fc2_b  = (const float*)d_in[14];

    float* x = (float*)d_out;

    float *p_qkv, *p_sc;
    bf16 *p_hh, *p_hl, *p_qh, *p_ql, *p_kh, *p_kl, *p_vth, *p_vtl;
    bf16 *p_ph, *p_pl, *p_ah, *p_al, *p_mh, *p_ml;
    bf16 *wqh, *wql, *wph, *wpl, *w1h, *w1l, *w2h, *w2l;
    cudaGetSymbolAddress((void**)&p_qkv, g_qkv);
    cudaGetSymbolAddress((void**)&p_sc,  g_scores);
    cudaGetSymbolAddress((void**)&p_hh,  g_hh);   cudaGetSymbolAddress((void**)&p_hl, g_hl);
    cudaGetSymbolAddress((void**)&p_qh,  g_qh);   cudaGetSymbolAddress((void**)&p_ql, g_ql);
    cudaGetSymbolAddress((void**)&p_kh,  g_kh);   cudaGetSymbolAddress((void**)&p_kl, g_kl);
    cudaGetSymbolAddress((void**)&p_vth, g_vth);  cudaGetSymbolAddress((void**)&p_vtl, g_vtl);
    cudaGetSymbolAddress((void**)&p_ph,  g_ph);   cudaGetSymbolAddress((void**)&p_pl, g_pl);
    cudaGetSymbolAddress((void**)&p_ah,  g_ah);   cudaGetSymbolAddress((void**)&p_al, g_al);
    cudaGetSymbolAddress((void**)&p_mh,  g_mh);   cudaGetSymbolAddress((void**)&p_ml, g_ml);
    cudaGetSymbolAddress((void**)&wqh, g_wqh);    cudaGetSymbolAddress((void**)&wql, g_wql);
    cudaGetSymbolAddress((void**)&wph, g_wph);    cudaGetSymbolAddress((void**)&wpl, g_wpl);
    cudaGetSymbolAddress((void**)&w1h, g_w1h);    cudaGetSymbolAddress((void**)&w1l, g_w1l);
    cudaGetSymbolAddress((void**)&w2h, g_w2h);    cudaGetSymbolAddress((void**)&w2l, g_w2l);

    cudaFuncSetAttribute((const void*)gemm_mma2<0>, cudaFuncAttributeMaxDynamicSharedMemorySize, GEMM2_SMEM);
    cudaFuncSetAttribute((const void*)gemm_mma2<1>, cudaFuncAttributeMaxDynamicSharedMemorySize, GEMM2_SMEM);
    cudaFuncSetAttribute((const void*)gemm_mma2<2>, cudaFuncAttributeMaxDynamicSharedMemorySize, GEMM2_SMEM);
    cudaFuncSetAttribute((const void*)gemm_mma2<4>, cudaFuncAttributeMaxDynamicSharedMemorySize, GEMM2_SMEM);
    cudaFuncSetAttribute((const void*)gemm_mma<3>,  cudaFuncAttributeMaxDynamicSharedMemorySize, GEMM_SMEM);

    cudaMemcpyAsync(x, hidden, (size_t)S_ * D_ * sizeof(float), cudaMemcpyDeviceToDevice);

    for (int l = 0; l < 2; l++) {
        const float* qw = qkv_w + (size_t)l * D_ * NQKV_;
        const float* qb = qkv_b + (size_t)l * NQKV_;
        const float* pw = proj_w + (size_t)l * D_ * D_;
        const float* pb = proj_b + (size_t)l * D_;
        const float* g1 = ln1_g + (size_t)l * D_;
        const float* b1 = ln1_b + (size_t)l * D_;
        const float* g2 = ln2_g + (size_t)l * D_;
        const float* b2 = ln2_b + (size_t)l * D_;
        const float* f1w = fc1_w + (size_t)l * D_ * I_;
        const float* f1b = fc1_b + (size_t)l * I_;
        const float* f2w = fc2_w + (size_t)l * I_ * D_;
        const float* f2b = fc2_b + (size_t)l * D_;

        // weight transpose+split
        wsplit_T_kernel<<<dim3(NQKV_ / 32, D_ / 32), dim3(32, 8)>>>(qw, wqh, wql, D_, NQKV_);
        wsplit_T_kernel<<<dim3(D_ / 32, D_ / 32), dim3(32, 8)>>>(pw, wph, wpl, D_, D_);
        wsplit_T_kernel<<<dim3(I_ / 32, D_ / 32), dim3(32, 8)>>>(f1w, w1h, w1l, D_, I_);
        wsplit_T_kernel<<<dim3(D_ / 32, I_ / 32), dim3(32, 8)>>>(f2w, w2h, w2l, I_, D_);

        // LN1 -> split
        ln_split_kernel<<<S_, 256>>>(x, g1, b1, p_hh, p_hl);

        // qkv = h @ W_qkv + b   (fp32 out)
        gemm_mma2<0><<<dim3(NQKV_ / 256, S_ / 128, 1), 512, GEMM2_SMEM>>>(
            p_hh, p_hl, wqh, wql, qb, p_qkv, nullptr, nullptr,
            D_, D_, D_, NQKV_, 0, 0, 0, 1.f);

        // RoPE + split + V^T (+zero pad)
        rope_split_kernel<<<(S_ * H_ * HDP_ + 255) / 256, 256>>>(
            p_qkv, cosp, sinp, p_qh, p_ql, p_kh, p_kl, p_vth, p_vtl);

        // scores = (Q @ K^T) * SCALE  per head (fp32), K padded to 96
        gemm_mma2<1><<<dim3(S_ / 256, S_ / 128, H_), 512, GEMM2_SMEM>>>(
            p_qh, p_ql, p_kh, p_kl, nullptr, p_sc, nullptr, nullptr,
            HDP_, HDP_, HDP_, S_,
            (long long)S_ * HDP_, (long long)S_ * HDP_, (long long)S_ * S_, SCALE_);

        // softmax -> split probs
        softmax_kernel<<<H_ * S_, 256>>>(p_sc, p_ph, p_pl);

        // O = P @ V  (bf16 split out into [S,D] with per-head col offset)
        gemm_mma<3><<<dim3(1, S_ / 128, H_), 256, GEMM_SMEM>>>(
            p_ph, p_pl, p_vth, p_vtl, nullptr, nullptr, p_ah, p_al,
            HD_, S_, S_, S_, D_,
            (long long)S_ * S_, (long long)HD_ * S_, (long long)HD_, 1.f);

        // x += O @ W_proj + b
        gemm_mma2<2><<<dim3(D_ / 256, S_ / 128, 1), 512, GEMM2_SMEM>>>(
            p_ah, p_al, wph, wpl, pb, x, nullptr, nullptr,
            D_, D_, D_, D_, 0, 0, 0, 1.f);

        // LN2 -> split
        ln_split_kernel<<<S_, 256>>>(x, g2, b2, p_hh, p_hl);

        // mlp = gelu(h @ W1 + b)  (bf16 split out)
        gemm_mma2<4><<<dim3(I_ / 256, S_ / 128, 1), 512, GEMM2_SMEM>>>(
            p_hh, p_hl, w1h, w1l, f1b, nullptr, p_mh, p_ml,
            D_, D_, D_, I_, 0, 0, 0, 1.f);

        // x += mlp @ W2 + b
        gemm_mma2<2><<<dim3(D_ / 256, S_ / 128, 1), 512, GEMM2_SMEM>>>(
            p_mh, p_ml, w2h, w2l, f2b, x, nullptr, nullptr,
            I_, I_, I_, D_, 0, 0, 0, 1.f);
    }
}